// round 1
// baseline (speedup 1.0000x reference)
#include <cuda_runtime.h>
#include <cstdint>

#define NITEMS 4096
#define TPB    512
#define EPT    (NITEMS / TPB)   // 8
#define NWARP  (TPB / 32)       // 16
#define NIT    40
#define CAP    600.0f
#define DAMP   1e-3f

__device__ __forceinline__ float frcp(float v) {
    float r;
    asm("rcp.approx.ftz.f32 %0, %1;" : "=f"(r) : "f"(v));
    return r;
}

__device__ __forceinline__ float warp_sum(float v) {
#pragma unroll
    for (int o = 16; o > 0; o >>= 1) v += __shfl_xor_sync(0xffffffffu, v, o);
    return v;
}

__device__ __forceinline__ float warp_max(float v) {
#pragma unroll
    for (int o = 16; o > 0; o >>= 1) v = fmaxf(v, __shfl_xor_sync(0xffffffffu, v, o));
    return v;
}

__global__ void __launch_bounds__(TPB, 1)
ipm_kernel(const float* __restrict__ costs,
           const float* __restrict__ wglob,
           float* __restrict__ out)
{
    __shared__ float sA[NWARP], sB[NWARP], sC[NWARP], sS[2];

    const int tid  = threadIdx.x;
    const int lane = tid & 31;
    const int wid  = tid >> 5;
    const long long b = blockIdx.x;
    const float* crow = costs + b * (long long)NITEMS;

    float c[EPT], w[EPT], x[EPT];

    // Load row (coalesced), negate costs, accumulate weight sum
    float wsum = 0.f;
#pragma unroll
    for (int i = 0; i < EPT; i++) {
        int j = i * TPB + tid;
        c[i] = -crow[j];
        w[i] = wglob[j];
        wsum += w[i];
    }
    // block-sum wsum
    wsum = warp_sum(wsum);
    if (lane == 0) sA[wid] = wsum;
    __syncthreads();
    if (tid < 32) {
        float a = (lane < NWARP) ? sA[lane] : 0.f;
        a = warp_sum(a);
        if (lane == 0) sS[0] = a;
    }
    __syncthreads();
    wsum = sS[0];

    const float x0 = CAP / wsum;   // equality-feasible interior start
#pragma unroll
    for (int i = 0; i < EPT; i++) x[i] = x0;

    float lam = 0.f;
    float mupow = 1.0f;

    float F1a[EPT], iHa[EPT], qa[EPT], ma[EPT];

#pragma unroll 1
    for (int it = 0; it < NIT; ++it) {
        const float muc = fmaxf(mupow, DAMP);
        mupow *= 0.5f;
        const float two_mu = 2.0f * muc;
        const float neg_mu = -muc;

        // ---------------- Pass A: F1, invH (mu-scaled), partial sums --------
        float s1 = 0.f, s2 = 0.f, s3 = 0.f;
#pragma unroll
        for (int i = 0; i < EPT; i++) {
            const float xi  = x[i];
            const float omx = 1.0f - xi;
            const float p   = xi * omx;            // x(1-x)
            const float q   = frcp(p);             // 1/(x(1-x))
            const float s   = fmaf(-2.0f, p, 1.0f); // x^2+(1-x)^2
            const float rs  = frcp(s);
            const float iH  = (p * p) * rs;        // = mu * (1/H)
            const float t   = fmaf(two_mu, xi, neg_mu);   // mu*(2x-1)
            const float f1  = fmaf(t, q, fmaf(lam, w[i], c[i])); // KKT residual
            const float wiH = w[i] * iH;
            s1 = fmaf(xi,  w[i], s1);   // sum x*w
            s2 = fmaf(wiH, f1,   s2);   // mu * sum (w/H)*F1
            s3 = fmaf(wiH, w[i], s3);   // mu * sum w^2/H
            F1a[i] = f1; iHa[i] = iH; qa[i] = q;
        }

        // ---------------- block reduce 3 sums -> dlam -----------------------
        s1 = warp_sum(s1); s2 = warp_sum(s2); s3 = warp_sum(s3);
        if (lane == 0) { sA[wid] = s1; sB[wid] = s2; sC[wid] = s3; }
        __syncthreads();
        if (tid < 32) {
            float a  = (lane < NWARP) ? sA[lane] : 0.f;
            float bb = (lane < NWARP) ? sB[lane] : 0.f;
            float cc = (lane < NWARP) ? sC[lane] : 0.f;
            a = warp_sum(a); bb = warp_sum(bb); cc = warp_sum(cc);
            if (lane == 0) {
                const float F2 = a - CAP;
                sS[0] = (muc * F2 - bb) / cc;    // dlam (Schur complement)
            }
        }
        __syncthreads();
        const float dlam = sS[0];

        // ---------------- Pass B: m = -mu*dx, boundary ratio ---------------
        float tmax = 0.f;
#pragma unroll
        for (int i = 0; i < EPT; i++) {
            const float u   = fmaf(dlam, w[i], F1a[i]);
            const float mm  = u * iHa[i];                 // -mu*dx
            const float rx  = (1.0f - x[i]) * qa[i];      // 1/x
            const float r1x = x[i] * qa[i];               // 1/(1-x)
            // mu * max(dx/(1-x), -dx/x)  (dx>0 <-> mm<0)
            tmax = fmaxf(tmax, fmaxf(mm * rx, -(mm * r1x)));
            ma[i] = mm;
        }
        tmax = warp_max(tmax);
        if (lane == 0) sA[wid] = tmax;
        __syncthreads();
        if (tid < 32) {
            float a = (lane < NWARP) ? sA[lane] : 0.f;
            a = warp_max(a);
            if (lane == 0) sS[1] = a;
        }
        __syncthreads();
        tmax = sS[1];

        const float alpha = (tmax > 0.f) ? fminf(1.0f, 0.99f * muc / tmax) : 1.0f;
        const float aom   = alpha / muc;                  // alpha/mu
#pragma unroll
        for (int i = 0; i < EPT; i++) x[i] = fmaf(-aom, ma[i], x[i]);
        lam = fmaf(alpha, dlam, lam);

        // Early exit: mu pinned at DAMP and relative step negligible.
        // Remaining iterations would each move x by < 1e-6 relative.
        if (muc <= DAMP) {
            if (tmax < 1e-6f * muc && fabsf(dlam) < 1e-6f * (1.0f + fabsf(lam)))
                break;
        }
    }

    // ---------------- KKT refine at mu = DAMP, out = x + dx ----------------
    {
        const float muc = DAMP;
        const float two_mu = 2.0f * muc;
        const float neg_mu = -muc;
        float s1 = 0.f, s2 = 0.f, s3 = 0.f;
#pragma unroll
        for (int i = 0; i < EPT; i++) {
            const float xi  = x[i];
            const float omx = 1.0f - xi;
            const float p   = xi * omx;
            const float q   = frcp(p);
            const float s   = fmaf(-2.0f, p, 1.0f);
            const float rs  = frcp(s);
            const float iH  = (p * p) * rs;
            const float t   = fmaf(two_mu, xi, neg_mu);
            const float f1  = fmaf(t, q, fmaf(lam, w[i], c[i]));
            const float wiH = w[i] * iH;
            s1 = fmaf(xi,  w[i], s1);
            s2 = fmaf(wiH, f1,   s2);
            s3 = fmaf(wiH, w[i], s3);
            F1a[i] = f1; iHa[i] = iH;
        }
        s1 = warp_sum(s1); s2 = warp_sum(s2); s3 = warp_sum(s3);
        if (lane == 0) { sA[wid] = s1; sB[wid] = s2; sC[wid] = s3; }
        __syncthreads();
        if (tid < 32) {
            float a  = (lane < NWARP) ? sA[lane] : 0.f;
            float bb = (lane < NWARP) ? sB[lane] : 0.f;
            float cc = (lane < NWARP) ? sC[lane] : 0.f;
            a = warp_sum(a); bb = warp_sum(bb); cc = warp_sum(cc);
            if (lane == 0) {
                const float F2 = a - CAP;
                sS[0] = (muc * F2 - bb) / cc;
            }
        }
        __syncthreads();
        const float dlam = sS[0];
        const float inv_mu = 1.0f / DAMP;

        float* orow = out + b * (long long)NITEMS;
#pragma unroll
        for (int i = 0; i < EPT; i++) {
            const float u  = fmaf(dlam, w[i], F1a[i]);
            const float mm = u * iHa[i];                 // -mu*dx
            orow[i * TPB + tid] = fmaf(-inv_mu, mm, x[i]); // x + dx
        }
    }
}

extern "C" void kernel_launch(void* const* d_in, const int* in_sizes, int n_in,
                              void* d_out, int out_size)
{
    // Identify inputs: costs is [B, 4096], weights is [4096]
    const float* costs = (const float*)d_in[0];
    const float* wv    = (const float*)d_in[1];
    int costs_elems = in_sizes[0];
    if (n_in >= 2 && in_sizes[0] == NITEMS && in_sizes[1] > NITEMS) {
        costs = (const float*)d_in[1];
        wv    = (const float*)d_in[0];
        costs_elems = in_sizes[1];
    }
    const int B = costs_elems / NITEMS;

    ipm_kernel<<<B, TPB>>>(costs, wv, (float*)d_out);
}

// round 2
// speedup vs baseline: 1.3939x; 1.3939x over previous
#include <cuda_runtime.h>
#include <cstdint>

#define NITEMS 4096
#define TPB    512
#define NWARP  16
#define NIT    40
#define CAP    600.0f
#define DAMP   1e-3f

typedef unsigned long long u64p;   // packed f32x2

__device__ __forceinline__ float frcp(float v) {
    float r;
    asm("rcp.approx.ftz.f32 %0, %1;" : "=f"(r) : "f"(v));
    return r;
}
__device__ __forceinline__ u64p pack2(float lo, float hi) {
    u64p r;
    asm("mov.b64 %0, {%1, %2};" : "=l"(r) : "f"(lo), "f"(hi));
    return r;
}
__device__ __forceinline__ void unpack2(u64p v, float& lo, float& hi) {
    asm("mov.b64 {%0, %1}, %2;" : "=f"(lo), "=f"(hi) : "l"(v));
}
__device__ __forceinline__ u64p mul2(u64p a, u64p b) {
    u64p r;
    asm("mul.rn.f32x2 %0, %1, %2;" : "=l"(r) : "l"(a), "l"(b));
    return r;
}
__device__ __forceinline__ u64p fma2(u64p a, u64p b, u64p c) {
    u64p r;
    asm("fma.rn.f32x2 %0, %1, %2, %3;" : "=l"(r) : "l"(a), "l"(b), "l"(c));
    return r;
}

__device__ __forceinline__ float wsum32(float v) {
#pragma unroll
    for (int o = 16; o > 0; o >>= 1) v += __shfl_xor_sync(0xffffffffu, v, o);
    return v;
}
__device__ __forceinline__ float wmax32(float v) {
#pragma unroll
    for (int o = 16; o > 0; o >>= 1) v = fmaxf(v, __shfl_xor_sync(0xffffffffu, v, o));
    return v;
}
// reduce 16 values duplicated across the warp (idx = lane&15): 4-step butterfly,
// every lane ends with the full result (no second barrier, no warp-0 stage).
__device__ __forceinline__ float bsum16(float v) {
#pragma unroll
    for (int o = 8; o > 0; o >>= 1) v += __shfl_xor_sync(0xffffffffu, v, o);
    return v;
}
__device__ __forceinline__ float bmax16(float v) {
#pragma unroll
    for (int o = 8; o > 0; o >>= 1) v = fmaxf(v, __shfl_xor_sync(0xffffffffu, v, o));
    return v;
}

// Pass A: per-pair barrier-KKT quantities, mu-scaled. One rcp per element:
//   p = x(1-x), s = 1-2p,  r = 1/(p^2 s)  =>  1/p = r p s,  mu/H = p^2/s = r p^4
__device__ __forceinline__ void passA(
    const float4* __restrict__ sc, const float4* __restrict__ sw, int tid,
    const u64p* xP, u64p* qS, u64p* wiS, u64p* fiS,
    float lam, float muc, u64p one2, u64p none2, u64p n22,
    float& o1, float& o2, float& o3)
{
    const u64p lam2 = pack2(lam, lam);
    const u64p tmu2 = pack2(2.0f * muc, 2.0f * muc);
    const u64p nmu2 = pack2(-muc, -muc);
    u64p s1 = 0ull, s2 = 0ull, s3 = 0ull;
#pragma unroll
    for (int h = 0; h < 2; h++) {
        const float4 cf = sc[h * TPB + tid];
        const float4 wf = sw[h * TPB + tid];
#pragma unroll
        for (int j = 0; j < 2; j++) {
            const int idx = h * 2 + j;
            const u64p cv = j ? pack2(cf.z, cf.w) : pack2(cf.x, cf.y);
            const u64p wv = j ? pack2(wf.z, wf.w) : pack2(wf.x, wf.y);
            const u64p xv = xP[idx];
            const u64p omx = fma2(xv, none2, one2);     // 1-x
            const u64p p   = mul2(xv, omx);             // x(1-x)
            const u64p s   = fma2(p, n22, one2);        // 1-2p
            const u64p p2  = mul2(p, p);
            const u64p arg = mul2(p2, s);
            float a0, a1; unpack2(arg, a0, a1);
            const u64p r   = pack2(frcp(a0), frcp(a1)); // 1/(p^2 s)
            const u64p q   = mul2(r, mul2(p, s));       // 1/p
            const u64p iH  = mul2(r, mul2(p2, p2));     // mu/H
            const u64p t   = fma2(tmu2, xv, nmu2);      // mu(2x-1)
            const u64p f1  = fma2(t, q, fma2(lam2, wv, cv));
            const u64p wiH = mul2(wv, iH);
            qS[idx]  = q;
            wiS[idx] = wiH;
            fiS[idx] = mul2(f1, iH);
            s1 = fma2(xv,  wv, s1);    // sum x w
            s2 = fma2(wiH, f1, s2);    // mu * sum (w/H) F1
            s3 = fma2(wiH, wv, s3);    // mu * sum w^2/H
        }
    }
    float lo, hi;
    unpack2(s1, lo, hi); o1 = lo + hi;
    unpack2(s2, lo, hi); o2 = lo + hi;
    unpack2(s3, lo, hi); o3 = lo + hi;
}

__device__ __forceinline__ float reduce_dlam(
    float s1, float s2, float s3, float muc,
    float* sA, float* sB, float* sC, int lane, int wid)
{
    s1 = wsum32(s1); s2 = wsum32(s2); s3 = wsum32(s3);
    if (lane == 0) { sA[wid] = s1; sB[wid] = s2; sC[wid] = s3; }
    __syncthreads();
    const float a = bsum16(sA[lane & 15]);
    const float b = bsum16(sB[lane & 15]);
    const float c = bsum16(sC[lane & 15]);
    return (muc * (a - CAP) - b) * frcp(c);   // scalar Schur
}

__global__ void __launch_bounds__(TPB, 2)
ipm_kernel(const float* __restrict__ costs,
           const float* __restrict__ wglob,
           float* __restrict__ out)
{
    __shared__ float4 sc[2 * TPB];   // -costs row, 16KB
    __shared__ float4 sw[2 * TPB];   // weights,    16KB
    __shared__ float sA[NWARP], sB[NWARP], sC[NWARP], sD[NWARP];

    const int tid = threadIdx.x, lane = tid & 31, wid = tid >> 5;
    const float* crow = costs + (size_t)blockIdx.x * NITEMS;

    float wsum;
    {
        const float4* cg = (const float4*)crow;
        const float4* wg = (const float4*)wglob;
        const float4 c0 = cg[tid], c1 = cg[TPB + tid];
        const float4 w0 = wg[tid], w1 = wg[TPB + tid];
        sc[tid]       = make_float4(-c0.x, -c0.y, -c0.z, -c0.w);
        sc[TPB + tid] = make_float4(-c1.x, -c1.y, -c1.z, -c1.w);
        sw[tid] = w0; sw[TPB + tid] = w1;
        wsum = ((w0.x + w0.y) + (w0.z + w0.w)) + ((w1.x + w1.y) + (w1.z + w1.w));
    }
    wsum = wsum32(wsum);
    if (lane == 0) sA[wid] = wsum;
    __syncthreads();
    wsum = bsum16(sA[lane & 15]);
    __syncthreads();   // protect sA reuse in iteration 0

    const float x0 = CAP / wsum;

    u64p xP[4], qS[4], wiS[4], fiS[4];
#pragma unroll
    for (int i = 0; i < 4; i++) xP[i] = pack2(x0, x0);

    const u64p one2  = pack2(1.0f, 1.0f);
    const u64p none2 = pack2(-1.0f, -1.0f);
    const u64p n22   = pack2(-2.0f, -2.0f);

    float lam = 0.0f, mupow = 1.0f;

#pragma unroll 1
    for (int it = 0; it < NIT; ++it) {
        const float muc = fmaxf(mupow, DAMP);
        mupow *= 0.5f;

        float s1, s2, s3;
        passA(sc, sw, tid, xP, qS, wiS, fiS, lam, muc, one2, none2, n22, s1, s2, s3);
        const float dlam = reduce_dlam(s1, s2, s3, muc, sA, sB, sC, lane, wid);
        const u64p dl2 = pack2(dlam, dlam);

        // fraction-to-boundary: mm = -mu*dx;  ratios via stored q = 1/(x(1-x))
        float tm = 0.0f;
#pragma unroll
        for (int idx = 0; idx < 4; idx++) {
            const u64p mm  = fma2(dl2, wiS[idx], fiS[idx]);
            const u64p omx = fma2(xP[idx], none2, one2);
            const u64p t1  = mul2(mm, mul2(omx, qS[idx]));      // mm/x
            const u64p t2  = mul2(mm, mul2(xP[idx], qS[idx]));  // mm/(1-x)
            float u0, u1, v0, v1;
            unpack2(t1, u0, u1); unpack2(t2, v0, v1);
            tm = fmaxf(tm, fmaxf(fmaxf(u0, u1), fmaxf(-v0, -v1)));
        }
        tm = wmax32(tm);
        if (lane == 0) sD[wid] = tm;
        __syncthreads();
        const float tmax = bmax16(sD[lane & 15]);

        const float alpha = (tmax > 0.0f) ? fminf(1.0f, 0.99f * muc * frcp(tmax)) : 1.0f;
        const float aom   = alpha * frcp(muc);
        const u64p na2 = pack2(-aom, -aom);
#pragma unroll
        for (int idx = 0; idx < 4; idx++) {
            const u64p mm = fma2(dl2, wiS[idx], fiS[idx]);
            xP[idx] = fma2(na2, mm, xP[idx]);
        }
        lam = fmaf(alpha, dlam, lam);

        // Early exit once mu is pinned and the relative step is negligible.
        if (muc <= DAMP) {
            if (tmax < 1e-6f * muc && fabsf(dlam) < 1e-6f * (1.0f + fabsf(lam)))
                break;
        }
    }

    // KKT refine at mu = DAMP: out = x + dx = x - mm/mu
    {
        float s1, s2, s3;
        passA(sc, sw, tid, xP, qS, wiS, fiS, lam, DAMP, one2, none2, n22, s1, s2, s3);
        const float dlam = reduce_dlam(s1, s2, s3, DAMP, sA, sB, sC, lane, wid);
        const u64p dl2 = pack2(dlam, dlam);
        const float inv_mu = 1.0f / DAMP;
        const u64p ni2 = pack2(-inv_mu, -inv_mu);

        float4* orow = (float4*)(out + (size_t)blockIdx.x * NITEMS);
#pragma unroll
        for (int h = 0; h < 2; h++) {
            float4 o;
            {
                const int idx = h * 2;
                const u64p mm = fma2(dl2, wiS[idx], fiS[idx]);
                const u64p ov = fma2(ni2, mm, xP[idx]);
                unpack2(ov, o.x, o.y);
            }
            {
                const int idx = h * 2 + 1;
                const u64p mm = fma2(dl2, wiS[idx], fiS[idx]);
                const u64p ov = fma2(ni2, mm, xP[idx]);
                unpack2(ov, o.z, o.w);
            }
            orow[h * TPB + tid] = o;
        }
    }
}

extern "C" void kernel_launch(void* const* d_in, const int* in_sizes, int n_in,
                              void* d_out, int out_size)
{
    const float* costs = (const float*)d_in[0];
    const float* wv    = (const float*)d_in[1];
    int costs_elems = in_sizes[0];
    if (n_in >= 2 && in_sizes[0] == NITEMS && in_sizes[1] > NITEMS) {
        costs = (const float*)d_in[1];
        wv    = (const float*)d_in[0];
        costs_elems = in_sizes[1];
    }
    const int B = costs_elems / NITEMS;
    ipm_kernel<<<B, TPB>>>(costs, wv, (float*)d_out);
}